// round 1
// baseline (speedup 1.0000x reference)
#include <cuda_runtime.h>
#include <math.h>

#define BB 32
#define TT 1024
#define JJ 256
#define DD 512
#define NCHUNK 8          // t-chunks for partial reductions (1024/128)

// ---------------- scratch (device globals; no allocation allowed) ----------
__device__ float g_S[BB * TT * JJ];      // 32 MB: S, later overwritten with P
__device__ float g_c1[BB * TT];
__device__ float g_q2[BB * JJ];
__device__ float g_m[BB * TT];           // row max over j
__device__ float g_pM[BB * NCHUNK * JJ]; // column partial max
__device__ float g_pZ[BB * NCHUNK * JJ]; // column partial sum
__device__ float g_M[BB * JJ];
__device__ float g_invZ[BB * JJ];
__device__ float g_bt[BB * TT];
__device__ float g_hp[BB * NCHUNK * DD];
__device__ float g_h[BB * DD];

// ---------------- K0: row dot products (c1 = C@w1, q2 = Q@w2) --------------
__global__ __launch_bounds__(256) void k_rowdot(const float* __restrict__ X,
                                                const float* __restrict__ w,
                                                float* __restrict__ out,
                                                int nrows) {
    int warp = (blockIdx.x * 256 + threadIdx.x) >> 5;
    int lane = threadIdx.x & 31;
    if (warp >= nrows) return;
    const float* row = X + (size_t)warp * DD;
    float s = 0.f;
#pragma unroll
    for (int i = 0; i < DD / 32; i++)
        s += row[lane + i * 32] * __ldg(&w[lane + i * 32]);
#pragma unroll
    for (int o = 16; o > 0; o >>= 1)
        s += __shfl_down_sync(0xffffffffu, s, o);
    if (lane == 0) out[warp] = s;
}

// ---------------- K1: S = (C .* w3) @ Q^T + c1 + q2 ------------------------
// Tile: BM=128 (t), BN=64 (j), BK=16, 256 threads, 8x4 per thread.
__global__ __launch_bounds__(256) void k_s_gemm(const float* __restrict__ C,
                                                const float* __restrict__ Q,
                                                const float* __restrict__ w3) {
    __shared__ float As[16][132];
    __shared__ float Bs[16][68];
    __shared__ float w3s[DD];

    const int tid = threadIdx.x;
    const int b  = blockIdx.z;
    const int t0 = blockIdx.y * 128;
    const int j0 = blockIdx.x * 64;

    w3s[tid]       = w3[tid];
    w3s[tid + 256] = w3[tid + 256];
    __syncthreads();

    const int tx = tid & 15, ty = tid >> 4;
    const int row0 = ty * 8, col0 = tx * 4;
    const int ar  = tid >> 2;   // A-load row (0..63), +64 for second
    const int ac4 = tid & 3;    // A-load float4-column

    float acc[8][4];
#pragma unroll
    for (int i = 0; i < 8; i++)
#pragma unroll
        for (int j = 0; j < 4; j++) acc[i][j] = 0.f;

    for (int k0 = 0; k0 < DD; k0 += 16) {
        // A tile: 128 x 16, multiply by w3 on store (transposed to As[k][t])
#pragma unroll
        for (int i = 0; i < 2; i++) {
            int r = ar + i * 64;
            float4 v = *(const float4*)(C + ((size_t)(b * TT + t0 + r)) * DD + k0 + ac4 * 4);
            As[ac4 * 4 + 0][r] = v.x * w3s[k0 + ac4 * 4 + 0];
            As[ac4 * 4 + 1][r] = v.y * w3s[k0 + ac4 * 4 + 1];
            As[ac4 * 4 + 2][r] = v.z * w3s[k0 + ac4 * 4 + 2];
            As[ac4 * 4 + 3][r] = v.w * w3s[k0 + ac4 * 4 + 3];
        }
        // B tile: 64 j-rows x 16 k, transposed to Bs[k][j]
        {
            int jr = tid >> 2, c4 = tid & 3;
            float4 v = *(const float4*)(Q + ((size_t)(b * JJ + j0 + jr)) * DD + k0 + c4 * 4);
            Bs[c4 * 4 + 0][jr] = v.x;
            Bs[c4 * 4 + 1][jr] = v.y;
            Bs[c4 * 4 + 2][jr] = v.z;
            Bs[c4 * 4 + 3][jr] = v.w;
        }
        __syncthreads();
#pragma unroll
        for (int kk = 0; kk < 16; kk++) {
            float4 a0 = *(const float4*)&As[kk][row0];
            float4 a1 = *(const float4*)&As[kk][row0 + 4];
            float4 bb = *(const float4*)&Bs[kk][col0];
            float a[8] = {a0.x, a0.y, a0.z, a0.w, a1.x, a1.y, a1.z, a1.w};
            float bv[4] = {bb.x, bb.y, bb.z, bb.w};
#pragma unroll
            for (int i = 0; i < 8; i++)
#pragma unroll
                for (int j = 0; j < 4; j++) acc[i][j] = fmaf(a[i], bv[j], acc[i][j]);
        }
        __syncthreads();
    }

    float q2v[4];
#pragma unroll
    for (int j = 0; j < 4; j++) q2v[j] = g_q2[b * JJ + j0 + col0 + j];
#pragma unroll
    for (int i = 0; i < 8; i++) {
        int t = t0 + row0 + i;
        float c1v = g_c1[b * TT + t];
        float4 o;
        o.x = acc[i][0] + c1v + q2v[0];
        o.y = acc[i][1] + c1v + q2v[1];
        o.z = acc[i][2] + c1v + q2v[2];
        o.w = acc[i][3] + c1v + q2v[3];
        *(float4*)&g_S[((size_t)(b * TT + t)) * JJ + j0 + col0] = o;
    }
}

// ---------------- K2a: row max over j (for b_t) -----------------------------
__global__ __launch_bounds__(256) void k_rowmax() {
    int row  = blockIdx.x * 8 + (threadIdx.x >> 5);
    int lane = threadIdx.x & 31;
    const float* r = &g_S[(size_t)row * JJ];
    float4 v1 = *(const float4*)&r[lane * 8];
    float4 v2 = *(const float4*)&r[lane * 8 + 4];
    float m = fmaxf(fmaxf(fmaxf(v1.x, v1.y), fmaxf(v1.z, v1.w)),
                    fmaxf(fmaxf(v2.x, v2.y), fmaxf(v2.z, v2.w)));
#pragma unroll
    for (int o = 16; o > 0; o >>= 1)
        m = fmaxf(m, __shfl_down_sync(0xffffffffu, m, o));
    if (lane == 0) g_m[row] = m;
}

// ---------------- K2b: column softmax partial stats (over t-chunk) ---------
__global__ __launch_bounds__(256) void k_colstats() {
    int b = blockIdx.y, chunk = blockIdx.x;
    int j = threadIdx.x;
    float M = -1e30f, Z = 0.f;
    for (int tt = 0; tt < TT / NCHUNK; tt++) {
        int t = chunk * (TT / NCHUNK) + tt;
        float v = g_S[((size_t)(b * TT + t)) * JJ + j];
        float nm = fmaxf(M, v);
        Z = Z * __expf(M - nm) + __expf(v - nm);
        M = nm;
    }
    g_pM[(b * NCHUNK + chunk) * JJ + j] = M;
    g_pZ[(b * NCHUNK + chunk) * JJ + j] = Z;
}

// ---------------- K2c: combine column partials ------------------------------
__global__ __launch_bounds__(256) void k_colcombine() {
    int b = blockIdx.x, j = threadIdx.x;
    float M = -1e30f;
#pragma unroll
    for (int c = 0; c < NCHUNK; c++) M = fmaxf(M, g_pM[(b * NCHUNK + c) * JJ + j]);
    float Z = 0.f;
#pragma unroll
    for (int c = 0; c < NCHUNK; c++)
        Z += g_pZ[(b * NCHUNK + c) * JJ + j] * __expf(g_pM[(b * NCHUNK + c) * JJ + j] - M);
    g_M[b * JJ + j]    = M;
    g_invZ[b * JJ + j] = 1.0f / Z;
}

// ---------------- K2d: b_t = softmax_t(m) -----------------------------------
__global__ __launch_bounds__(256) void k_bt() {
    __shared__ float red[256];
    int b = blockIdx.x, tid = threadIdx.x;
    float mv[4];
#pragma unroll
    for (int i = 0; i < 4; i++) mv[i] = g_m[b * TT + tid + i * 256];
    float mx = fmaxf(fmaxf(mv[0], mv[1]), fmaxf(mv[2], mv[3]));
    red[tid] = mx;
    __syncthreads();
    for (int s = 128; s > 0; s >>= 1) {
        if (tid < s) red[tid] = fmaxf(red[tid], red[tid + s]);
        __syncthreads();
    }
    float bmax = red[0];
    __syncthreads();
    float e[4], ssum = 0.f;
#pragma unroll
    for (int i = 0; i < 4; i++) { e[i] = __expf(mv[i] - bmax); ssum += e[i]; }
    red[tid] = ssum;
    __syncthreads();
    for (int s = 128; s > 0; s >>= 1) {
        if (tid < s) red[tid] += red[tid + s];
        __syncthreads();
    }
    float inv = 1.0f / red[0];
#pragma unroll
    for (int i = 0; i < 4; i++) g_bt[b * TT + tid + i * 256] = e[i] * inv;
}

// ---------------- K2e: h partials: sum_t bt[t]*C[t,d] over t-chunk ----------
__global__ __launch_bounds__(256) void k_hpart(const float* __restrict__ C) {
    __shared__ float bts[TT / NCHUNK];
    int b = blockIdx.y, chunk = blockIdx.x;
    int tid = threadIdx.x;
    if (tid < TT / NCHUNK) bts[tid] = g_bt[b * TT + chunk * (TT / NCHUNK) + tid];
    __syncthreads();
    float a0 = 0.f, a1 = 0.f;
    for (int tt = 0; tt < TT / NCHUNK; tt++) {
        int t = chunk * (TT / NCHUNK) + tt;
        const float* cr = C + ((size_t)(b * TT + t)) * DD;
        a0 = fmaf(bts[tt], cr[tid], a0);
        a1 = fmaf(bts[tt], cr[tid + 256], a1);
    }
    g_hp[(b * NCHUNK + chunk) * DD + tid]       = a0;
    g_hp[(b * NCHUNK + chunk) * DD + tid + 256] = a1;
}

__global__ __launch_bounds__(512) void k_hcombine() {
    int b = blockIdx.x, d = threadIdx.x;
    float s = 0.f;
#pragma unroll
    for (int c = 0; c < NCHUNK; c++) s += g_hp[(b * NCHUNK + c) * DD + d];
    g_h[b * DD + d] = s;
}

// ---------------- K2f: P = exp(S - M[j]) * invZ[j]  (in place) --------------
__global__ __launch_bounds__(256) void k_ptrans() {
    int idx4 = blockIdx.x * 256 + threadIdx.x;
    size_t flat = (size_t)idx4 * 4;
    int j = (int)(flat & (JJ - 1));
    int row = (int)(flat >> 8);
    int b = row >> 10;
    float4 v  = *(float4*)&g_S[flat];
    float4 Mv = *(const float4*)&g_M[b * JJ + j];
    float4 iz = *(const float4*)&g_invZ[b * JJ + j];
    v.x = __expf(v.x - Mv.x) * iz.x;
    v.y = __expf(v.y - Mv.y) * iz.y;
    v.z = __expf(v.z - Mv.z) * iz.z;
    v.w = __expf(v.w - Mv.w) * iz.w;
    *(float4*)&g_S[flat] = v;
}

// ---------------- K3: U = P @ Q, write all 4 segments of G ------------------
__global__ __launch_bounds__(256) void k_u_gemm(const float* __restrict__ C,
                                                const float* __restrict__ Q,
                                                float* __restrict__ G) {
    __shared__ float As[16][132];
    __shared__ float Bs[16][68];

    const int tid = threadIdx.x;
    const int b  = blockIdx.z;
    const int t0 = blockIdx.y * 128;
    const int d0 = blockIdx.x * 64;

    const int tx = tid & 15, ty = tid >> 4;
    const int row0 = ty * 8, col0 = tx * 4;
    const int ar  = tid >> 2;
    const int ac4 = tid & 3;

    float acc[8][4];
#pragma unroll
    for (int i = 0; i < 8; i++)
#pragma unroll
        for (int j = 0; j < 4; j++) acc[i][j] = 0.f;

    for (int k0 = 0; k0 < JJ; k0 += 16) {
        // A tile: P 128 x 16 (transposed)
#pragma unroll
        for (int i = 0; i < 2; i++) {
            int r = ar + i * 64;
            float4 v = *(const float4*)&g_S[((size_t)(b * TT + t0 + r)) * JJ + k0 + ac4 * 4];
            As[ac4 * 4 + 0][r] = v.x;
            As[ac4 * 4 + 1][r] = v.y;
            As[ac4 * 4 + 2][r] = v.z;
            As[ac4 * 4 + 3][r] = v.w;
        }
        // B tile: Q rows (k0..k0+15) x 64 d, stored direct
        {
            int rb = tid >> 4, c4 = tid & 15;
            float4 v = *(const float4*)(Q + ((size_t)(b * JJ + k0 + rb)) * DD + d0 + c4 * 4);
            *(float4*)&Bs[rb][c4 * 4] = v;
        }
        __syncthreads();
#pragma unroll
        for (int kk = 0; kk < 16; kk++) {
            float4 a0 = *(const float4*)&As[kk][row0];
            float4 a1 = *(const float4*)&As[kk][row0 + 4];
            float4 bb = *(const float4*)&Bs[kk][col0];
            float a[8] = {a0.x, a0.y, a0.z, a0.w, a1.x, a1.y, a1.z, a1.w};
            float bv[4] = {bb.x, bb.y, bb.z, bb.w};
#pragma unroll
            for (int i = 0; i < 8; i++)
#pragma unroll
                for (int j = 0; j < 4; j++) acc[i][j] = fmaf(a[i], bv[j], acc[i][j]);
        }
        __syncthreads();
    }

    float4 hv = *(const float4*)&g_h[b * DD + d0 + col0];
#pragma unroll
    for (int i = 0; i < 8; i++) {
        int t = t0 + row0 + i;
        float4 cv = *(const float4*)(C + ((size_t)(b * TT + t)) * DD + d0 + col0);
        size_t gb = ((size_t)(b * TT + t)) * (4 * DD);
        float4 u = {acc[i][0], acc[i][1], acc[i][2], acc[i][3]};
        *(float4*)&G[gb + d0 + col0]            = cv;
        *(float4*)&G[gb + DD + d0 + col0]       = u;
        float4 cu = {cv.x * u.x, cv.y * u.y, cv.z * u.z, cv.w * u.w};
        *(float4*)&G[gb + 2 * DD + d0 + col0]   = cu;
        float4 ch = {cv.x * hv.x, cv.y * hv.y, cv.z * hv.z, cv.w * hv.w};
        *(float4*)&G[gb + 3 * DD + d0 + col0]   = ch;
    }
}

// ---------------- launch ----------------------------------------------------
extern "C" void kernel_launch(void* const* d_in, const int* in_sizes, int n_in,
                              void* d_out, int out_size) {
    const float* C  = (const float*)d_in[0];   // context (32,1024,512)
    const float* Q  = (const float*)d_in[1];   // query   (32,256,512)
    const float* wa = (const float*)d_in[2];   // w_alpha (1536)
    float* G = (float*)d_out;

    float* d_c1;   cudaGetSymbolAddress((void**)&d_c1, g_c1);
    float* d_q2;   cudaGetSymbolAddress((void**)&d_q2, g_q2);

    // c1 = C @ w1, q2 = Q @ w2
    k_rowdot<<<(BB * TT) / 8, 256>>>(C, wa, d_c1, BB * TT);
    k_rowdot<<<(BB * JJ) / 8, 256>>>(Q, wa + DD, d_q2, BB * JJ);

    // S = (C .* w3) @ Q^T + c1 + q2
    dim3 g1(JJ / 64, TT / 128, BB);
    k_s_gemm<<<g1, 256>>>(C, Q, wa + 2 * DD);

    // reductions
    k_rowmax<<<(BB * TT) / 8, 256>>>();
    dim3 g2(NCHUNK, BB);
    k_colstats<<<g2, 256>>>();
    k_colcombine<<<BB, 256>>>();
    k_bt<<<BB, 256>>>();
    k_ptrans<<<(BB * TT * JJ) / 4 / 256, 256>>>();
    k_hpart<<<g2, 256>>>(C);
    k_hcombine<<<BB, 512>>>();

    // U = P @ Q + full G epilogue
    dim3 g3(DD / 64, TT / 128, BB);
    k_u_gemm<<<g3, 256>>>(C, Q, G);
}

// round 3
// speedup vs baseline: 1.6810x; 1.6810x over previous
#include <cuda_runtime.h>
#include <cuda_bf16.h>
#include <math.h>
#include <stdint.h>

#define BB 32
#define TT 1024
#define JJ 256
#define DD 512
#define NCHUNK 8

// ---------------- scratch (device globals) ----------------------------------
__device__ float g_S[BB * TT * JJ];      // raw S (32 MB)
__device__ float g_c1[BB * TT];
__device__ float g_q2[BB * JJ];
__device__ float g_m[BB * TT];
__device__ float g_pM[BB * NCHUNK * JJ];
__device__ float g_pZ[BB * NCHUNK * JJ];
__device__ float g_M[BB * JJ];
__device__ float g_invZ[BB * JJ];
__device__ float g_bt[BB * TT];
__device__ float g_hp[BB * NCHUNK * DD];
__device__ float g_h[BB * DD];

// ---------------- helpers ----------------------------------------------------
__device__ __forceinline__ uint32_t smem_u32(const void* p) {
    uint32_t a;
    asm("{ .reg .u64 t; cvta.to.shared.u64 t, %1; cvt.u32.u64 %0, t; }" : "=r"(a) : "l"(p));
    return a;
}
__device__ __forceinline__ void ldmx4(uint32_t* r, uint32_t a) {
    asm volatile("ldmatrix.sync.aligned.m8n8.x4.shared.b16 {%0,%1,%2,%3}, [%4];"
                 : "=r"(r[0]), "=r"(r[1]), "=r"(r[2]), "=r"(r[3]) : "r"(a));
}
__device__ __forceinline__ void ldmx4t(uint32_t* r, uint32_t a) {
    asm volatile("ldmatrix.sync.aligned.m8n8.x4.trans.shared.b16 {%0,%1,%2,%3}, [%4];"
                 : "=r"(r[0]), "=r"(r[1]), "=r"(r[2]), "=r"(r[3]) : "r"(a));
}
__device__ __forceinline__ void mma_bf16(float* c, const uint32_t* a, uint32_t b0, uint32_t b1) {
    asm volatile(
        "mma.sync.aligned.m16n8k16.row.col.f32.bf16.bf16.f32 "
        "{%0,%1,%2,%3}, {%4,%5,%6,%7}, {%8,%9}, {%0,%1,%2,%3};"
        : "+f"(c[0]), "+f"(c[1]), "+f"(c[2]), "+f"(c[3])
        : "r"(a[0]), "r"(a[1]), "r"(a[2]), "r"(a[3]), "r"(b0), "r"(b1));
}
__device__ __forceinline__ void split2(float v, __nv_bfloat16& h, __nv_bfloat16& l) {
    h = __float2bfloat16(v);
    l = __float2bfloat16(v - __bfloat162float(h));
}
// convert 8 floats -> 16B hi + 16B lo
__device__ __forceinline__ void conv8(const float* v, uint4* hi, uint4* lo) {
    __align__(16) __nv_bfloat16 h8[8], l8[8];
#pragma unroll
    for (int e = 0; e < 8; e++) split2(v[e], h8[e], l8[e]);
    *hi = *(uint4*)h8;
    *lo = *(uint4*)l8;
}

// ---------------- K0: row dot products --------------------------------------
__global__ __launch_bounds__(256) void k_rowdot(const float* __restrict__ X,
                                                const float* __restrict__ w,
                                                float* __restrict__ out, int nrows) {
    int warp = (blockIdx.x * 256 + threadIdx.x) >> 5;
    int lane = threadIdx.x & 31;
    if (warp >= nrows) return;
    const float* row = X + (size_t)warp * DD;
    float s = 0.f;
#pragma unroll
    for (int i = 0; i < DD / 32; i++)
        s += row[lane + i * 32] * __ldg(&w[lane + i * 32]);
#pragma unroll
    for (int o = 16; o > 0; o >>= 1) s += __shfl_down_sync(0xffffffffu, s, o);
    if (lane == 0) out[warp] = s;
}

// ---------------- S-GEMM (HMMA): S[128t x 128j] = (C.*w3) @ Q^T + c1 + q2 ----
// Tiles: A 128x32 (rows=t, k=d), B 128x32 (rows=j, k=d). Rows = 128B:
// chunks 0-3 = hi bf16, 4-7 = lo bf16; swizzle c' = c ^ (r&7).
__global__ __launch_bounds__(256) void k_s_mma(const float* __restrict__ C,
                                               const float* __restrict__ Q,
                                               const float* __restrict__ w3) {
    __shared__ __align__(16) char sAt[128 * 128];
    __shared__ __align__(16) char sBt[128 * 128];
    __shared__ float w3s[512];
    __shared__ float c1s[128];
    __shared__ float q2s[128];

    const int tid = threadIdx.x, lane = tid & 31, wid = tid >> 5;
    const int b = blockIdx.z, t0 = blockIdx.y * 128, j0 = blockIdx.x * 128;

    w3s[tid] = w3[tid];
    w3s[tid + 256] = w3[tid + 256];
    if (tid < 128) {
        c1s[tid] = g_c1[b * TT + t0 + tid];
        q2s[tid] = g_q2[b * JJ + j0 + tid];
    }

    const int sr = tid >> 2, sc = tid & 3;     // staging: rows sr, sr+64; chunk sc (8 floats)
    const float* Ab = C + ((size_t)(b * TT + t0 + sr)) * DD + sc * 8;
    const float* Bb = Q + ((size_t)(b * JJ + j0 + sr)) * DD + sc * 8;

    float4 ra0, ra1, ra2, ra3, rb0, rb1, rb2, rb3;
    ra0 = *(const float4*)(Ab);                     ra1 = *(const float4*)(Ab + 4);
    ra2 = *(const float4*)(Ab + (size_t)64 * DD);   ra3 = *(const float4*)(Ab + (size_t)64 * DD + 4);
    rb0 = *(const float4*)(Bb);                     rb1 = *(const float4*)(Bb + 4);
    rb2 = *(const float4*)(Bb + (size_t)64 * DD);   rb3 = *(const float4*)(Bb + (size_t)64 * DD + 4);

    const int wm = wid >> 2, wn = wid & 3;
    float acc[4][4][4];
#pragma unroll
    for (int i = 0; i < 4; i++)
#pragma unroll
        for (int j = 0; j < 4; j++)
#pragma unroll
            for (int e = 0; e < 4; e++) acc[i][j][e] = 0.f;

    const uint32_t sAb = smem_u32(sAt), sBb = smem_u32(sBt);
    const int lsw = lane & 7;                        // row&7 for all ldmatrix rows
    const int arow = wm * 64 + (lane & 7) + ((lane >> 3) & 1) * 8;  // + mi*16
    const int ack  = lane >> 4;                      // k-chunk half
    const int brow = wn * 32 + (lane & 7) + ((lane >> 4) & 1) * 8;  // + ni2*16
    const int bck  = (lane >> 3) & 1;
    const int ssw  = sr & 7;

#pragma unroll 1
    for (int kc = 0; kc < 16; kc++) {
        __syncthreads();
        // STS A (apply w3), rows sr and sr+64
        {
            const float* w = &w3s[kc * 32 + sc * 8];
            float v[8] = {ra0.x, ra0.y, ra0.z, ra0.w, ra1.x, ra1.y, ra1.z, ra1.w};
#pragma unroll
            for (int e = 0; e < 8; e++) v[e] *= w[e];
            uint4 hi, lo; conv8(v, &hi, &lo);
            *(uint4*)(sAt + sr * 128 + ((sc ^ ssw) << 4)) = hi;
            *(uint4*)(sAt + sr * 128 + (((sc + 4) ^ ssw) << 4)) = lo;
            float v2[8] = {ra2.x, ra2.y, ra2.z, ra2.w, ra3.x, ra3.y, ra3.z, ra3.w};
#pragma unroll
            for (int e = 0; e < 8; e++) v2[e] *= w[e];
            conv8(v2, &hi, &lo);
            *(uint4*)(sAt + (sr + 64) * 128 + ((sc ^ ssw) << 4)) = hi;
            *(uint4*)(sAt + (sr + 64) * 128 + (((sc + 4) ^ ssw) << 4)) = lo;
        }
        // STS B
        {
            float v[8] = {rb0.x, rb0.y, rb0.z, rb0.w, rb1.x, rb1.y, rb1.z, rb1.w};
            uint4 hi, lo; conv8(v, &hi, &lo);
            *(uint4*)(sBt + sr * 128 + ((sc ^ ssw) << 4)) = hi;
            *(uint4*)(sBt + sr * 128 + (((sc + 4) ^ ssw) << 4)) = lo;
            float v2[8] = {rb2.x, rb2.y, rb2.z, rb2.w, rb3.x, rb3.y, rb3.z, rb3.w};
            conv8(v2, &hi, &lo);
            *(uint4*)(sBt + (sr + 64) * 128 + ((sc ^ ssw) << 4)) = hi;
            *(uint4*)(sBt + (sr + 64) * 128 + (((sc + 4) ^ ssw) << 4)) = lo;
        }
        __syncthreads();
        if (kc < 15) {
            const float* pa = Ab + (kc + 1) * 32;
            const float* pb = Bb + (kc + 1) * 32;
            ra0 = *(const float4*)(pa);                   ra1 = *(const float4*)(pa + 4);
            ra2 = *(const float4*)(pa + (size_t)64 * DD); ra3 = *(const float4*)(pa + (size_t)64 * DD + 4);
            rb0 = *(const float4*)(pb);                   rb1 = *(const float4*)(pb + 4);
            rb2 = *(const float4*)(pb + (size_t)64 * DD); rb3 = *(const float4*)(pb + (size_t)64 * DD + 4);
        }
#pragma unroll
        for (int ks = 0; ks < 2; ks++) {
            uint32_t Ah[4][4], Al[4][4], Bf[2][4];
            const int ca = ks * 2 + ack;
            const int cb = ks * 2 + bck;
#pragma unroll
            for (int mi = 0; mi < 4; mi++)
                ldmx4(Ah[mi], sAb + (arow + mi * 16) * 128 + ((ca ^ lsw) << 4));
#pragma unroll
            for (int mi = 0; mi < 4; mi++)
                ldmx4(Al[mi], sAb + (arow + mi * 16) * 128 + (((ca + 4) ^ lsw) << 4));
#pragma unroll
            for (int n2 = 0; n2 < 2; n2++)
                ldmx4(Bf[n2], sBb + (brow + n2 * 16) * 128 + ((cb ^ lsw) << 4));
#pragma unroll
            for (int mi = 0; mi < 4; mi++)
#pragma unroll
                for (int ni = 0; ni < 4; ni++) {
                    const uint32_t* bp = &Bf[ni >> 1][(ni & 1) * 2];
                    mma_bf16(acc[mi][ni], Ah[mi], bp[0], bp[1]);
                }
#pragma unroll
            for (int mi = 0; mi < 4; mi++)
#pragma unroll
                for (int ni = 0; ni < 4; ni++) {
                    const uint32_t* bp = &Bf[ni >> 1][(ni & 1) * 2];
                    mma_bf16(acc[mi][ni], Al[mi], bp[0], bp[1]);
                }
#pragma unroll
            for (int n2 = 0; n2 < 2; n2++)
                ldmx4(Bf[n2], sBb + (brow + n2 * 16) * 128 + (((cb + 4) ^ lsw) << 4));
#pragma unroll
            for (int mi = 0; mi < 4; mi++)
#pragma unroll
                for (int ni = 0; ni < 4; ni++) {
                    const uint32_t* bp = &Bf[ni >> 1][(ni & 1) * 2];
                    mma_bf16(acc[mi][ni], Ah[mi], bp[0], bp[1]);
                }
        }
    }

    // epilogue: += c1 + q2, direct stores (g_S is L2-resident)
    const int g = lane >> 2, tc = (lane & 3) * 2;
#pragma unroll
    for (int mi = 0; mi < 4; mi++) {
        const int tl = wm * 64 + mi * 16 + g;
        const float c1a = c1s[tl], c1b = c1s[tl + 8];
        float* row0 = &g_S[((size_t)(b * TT + t0 + tl)) * JJ + j0];
        float* row1 = row0 + (size_t)8 * JJ;
#pragma unroll
        for (int ni = 0; ni < 4; ni++) {
            const int jl = wn * 32 + ni * 8 + tc;
            const float q2a = q2s[jl], q2b = q2s[jl + 1];
            float2 o0 = {acc[mi][ni][0] + c1a + q2a, acc[mi][ni][1] + c1a + q2b};
            float2 o1 = {acc[mi][ni][2] + c1b + q2a, acc[mi][ni][3] + c1b + q2b};
            *(float2*)(row0 + jl) = o0;
            *(float2*)(row1 + jl) = o1;
        }
    }
}

// ---------------- small reduction kernels (proven in round 1) ----------------
__global__ __launch_bounds__(256) void k_rowmax() {
    int row = blockIdx.x * 8 + (threadIdx.x >> 5);
    int lane = threadIdx.x & 31;
    const float* r = &g_S[(size_t)row * JJ];
    float4 v1 = *(const float4*)&r[lane * 8];
    float4 v2 = *(const float4*)&r[lane * 8 + 4];
    float m = fmaxf(fmaxf(fmaxf(v1.x, v1.y), fmaxf(v1.z, v1.w)),
                    fmaxf(fmaxf(v2.x, v2.y), fmaxf(v2.z, v2.w)));
#pragma unroll
    for (int o = 16; o > 0; o >>= 1) m = fmaxf(m, __shfl_down_sync(0xffffffffu, m, o));
    if (lane == 0) g_m[row] = m;
}
__global__ __launch_bounds__(256) void k_colstats() {
    int b = blockIdx.y, chunk = blockIdx.x;
    int j = threadIdx.x;
    float M = -1e30f, Z = 0.f;
    for (int tt = 0; tt < TT / NCHUNK; tt++) {
        int t = chunk * (TT / NCHUNK) + tt;
        float v = g_S[((size_t)(b * TT + t)) * JJ + j];
        float nm = fmaxf(M, v);
        Z = Z * __expf(M - nm) + __expf(v - nm);
        M = nm;
    }
    g_pM[(b * NCHUNK + chunk) * JJ + j] = M;
    g_pZ[(b * NCHUNK + chunk) * JJ + j] = Z;
}
__global__ __launch_bounds__(256) void k_colcombine() {
    int b = blockIdx.x, j = threadIdx.x;
    float M = -1e30f;
#pragma unroll
    for (int c = 0; c < NCHUNK; c++) M = fmaxf(M, g_pM[(b * NCHUNK + c) * JJ + j]);
    float Z = 0.f;
#pragma unroll
    for (int c = 0; c < NCHUNK; c++)
        Z += g_pZ[(b * NCHUNK + c) * JJ + j] * __expf(g_pM[(b * NCHUNK + c) * JJ + j] - M);
    g_M[b * JJ + j] = M;
    g_invZ[b * JJ + j] = 1.0f / Z;
}
__global__ __launch_bounds__(256) void k_bt() {
    __shared__ float red[256];
    int b = blockIdx.x, tid = threadIdx.x;
    float mv[4];
#pragma unroll
    for (int i = 0; i < 4; i++) mv[i] = g_m[b * TT + tid + i * 256];
    float mx = fmaxf(fmaxf(mv[0], mv[1]), fmaxf(mv[2], mv[3]));
    red[tid] = mx;
    __syncthreads();
    for (int s = 128; s > 0; s >>= 1) {
        if (tid < s) red[tid] = fmaxf(red[tid], red[tid + s]);
        __syncthreads();
    }
    float bmax = red[0];
    __syncthreads();
    float e[4], ssum = 0.f;
#pragma unroll
    for (int i = 0; i < 4; i++) { e[i] = __expf(mv[i] - bmax); ssum += e[i]; }
    red[tid] = ssum;
    __syncthreads();
    for (int s = 128; s > 0; s >>= 1) {
        if (tid < s) red[tid] += red[tid + s];
        __syncthreads();
    }
    float inv = 1.0f / red[0];
#pragma unroll
    for (int i = 0; i < 4; i++) g_bt[b * TT + tid + i * 256] = e[i] * inv;
}
__global__ __launch_bounds__(256) void k_hpart(const float* __restrict__ C) {
    __shared__ float bts[TT / NCHUNK];
    int b = blockIdx.y, chunk = blockIdx.x;
    int tid = threadIdx.x;
    if (tid < TT / NCHUNK) bts[tid] = g_bt[b * TT + chunk * (TT / NCHUNK) + tid];
    __syncthreads();
    float a0 = 0.f, a1 = 0.f;
    for (int tt = 0; tt < TT / NCHUNK; tt++) {
        int t = chunk * (TT / NCHUNK) + tt;
        const float* cr = C + ((size_t)(b * TT + t)) * DD;
        a0 = fmaf(bts[tt], cr[tid], a0);
        a1 = fmaf(bts[tt], cr[tid + 256], a1);
    }
    g_hp[(b * NCHUNK + chunk) * DD + tid] = a0;
    g_hp[(b * NCHUNK + chunk) * DD + tid + 256] = a1;
}
__global__ __launch_bounds__(512) void k_hcombine() {
    int b = blockIdx.x, d = threadIdx.x;
    float s = 0.f;
#pragma unroll
    for (int c = 0; c < NCHUNK; c++) s += g_hp[(b * NCHUNK + c) * DD + d];
    g_h[b * DD + d] = s;
}

// ---------------- U-GEMM (HMMA): U[128t x 128d] = softmax(S) @ Q -------------
// A tile: P 128x32 (rows=t, k=j) — same layout as S-GEMM A.
// B tile: Q 32x128 (rows=k=j, cols=d), hi & lo tiles, 256B rows,
//         swizzle c' = (c&8) | ((c ^ (r&7)) & 7).  B frags via ldmatrix.trans.
#define U_DSMEM 65536
__global__ __launch_bounds__(256) void k_u_mma(const float* __restrict__ C,
                                               const float* __restrict__ Q,
                                               float* __restrict__ G) {
    extern __shared__ __align__(16) char us[];
    __shared__ float Ms[256], iZs[256], hs[128];

    const int tid = threadIdx.x, lane = tid & 31, wid = tid >> 5;
    const int b = blockIdx.z, t0 = blockIdx.y * 128, d0 = blockIdx.x * 128;

    Ms[tid] = g_M[b * JJ + tid];
    iZs[tid] = g_invZ[b * JJ + tid];
    if (tid < 128) hs[tid] = g_h[b * DD + d0 + tid];

    char* sAt = us;                 // 16 KB
    char* sBh = us + 16384;         // 8 KB
    char* sBl = us + 24576;         // 8 KB
    const uint32_t sAb = smem_u32(sAt), sBhb = smem_u32(sBh), sBlb = smem_u32(sBl);

    const int sr = tid >> 2, sc = tid & 3;          // A staging
    const int rB = tid >> 4, cB = tid & 15;         // B staging: rows rB, rB+16
    const float* Sb = g_S + ((size_t)(b * TT + t0 + sr)) * JJ + sc * 8;
    const float* Qb = Q + ((size_t)(b * JJ + rB)) * DD + d0 + cB * 8;

    float4 ra0, ra1, ra2, ra3, rb0, rb1, rb2, rb3;
    ra0 = *(const float4*)(Sb);                     ra1 = *(const float4*)(Sb + 4);
    ra2 = *(const float4*)(Sb + (size_t)64 * JJ);   ra3 = *(const float4*)(Sb + (size_t)64 * JJ + 4);
    rb0 = *(const float4*)(Qb);                     rb1 = *(const float4*)(Qb + 4);
    rb2 = *(const float4*)(Qb + (size_t)16 * DD);   rb3 = *(const float4*)(Qb + (size_t)16 * DD + 4);

    const int wm = wid >> 2, wn = wid & 3;
    float acc[4][4][4];
#pragma unroll
    for (int i = 0; i < 4; i++)
#pragma unroll
        for (int j = 0; j < 4; j++)
#pragma unroll
            for (int e = 0; e < 4; e++) acc[i][j][e] = 0.f;

    const int lsw = lane & 7;
    const int arow = wm * 64 + (lane & 7) + ((lane >> 3) & 1) * 8;
    const int ack = lane >> 4;
    const int bkrow = (lane & 7) + ((lane >> 3) & 1) * 8;   // + ks*16
    const int bcn = wn * 4 + (lane >> 4);                   // + ni2*2 (16B chunks of d)
    const int ssw = sr & 7, bsw = rB & 7;

#pragma unroll 1
    for (int kc = 0; kc < 8; kc++) {
        __syncthreads();
        // STS A with fused softmax transform
        {
            const int jb = kc * 32 + sc * 8;
            float v[8] = {ra0.x, ra0.y, ra0.z, ra0.w, ra1.x, ra1.y, ra1.z, ra1.w};
#pragma unroll
            for (int e = 0; e < 8; e++) v[e] = __expf(v[e] - Ms[jb + e]) * iZs[jb + e];
            uint4 hi, lo; conv8(v, &hi, &lo);
            *(uint4*)(sAt + sr * 128 + ((sc ^ ssw) << 4)) = hi;
            *(uint4*)(sAt + sr * 128 + (((sc + 4) ^ ssw) << 4)) = lo;
            float v2[8] = {ra2.x, ra2.y, ra2.z, ra2.w, ra3.x, ra3.y, ra3.z, ra3.w};
#pragma unroll
            for (int e = 0; e < 8; e++) v2[e] = __expf(v2[e] - Ms[jb + e]) * iZs[jb + e];
            conv8(v2, &hi, &lo);
            *(uint4*)(sAt + (sr + 64) * 128 + ((sc ^ ssw) << 4)) = hi;
            *(uint4*)(sAt + (sr + 64) * 128 + (((sc + 4) ^ ssw) << 4)) = lo;
        }
        // STS B hi/lo tiles (rows rB, rB+16)
        {
            const int c1o = (((cB ^ bsw) & 7) | (cB & 8)) << 4;
            float v[8] = {rb0.x, rb0.y, rb0.z, rb0.w, rb1.x, rb1.y, rb1.z, rb1.w};
            uint4 hi, lo; conv8(v, &hi, &lo);
            *(uint4*)(sBh + rB * 256 + c1o) = hi;
            *(uint4*)(sBl + rB * 256 + c1o) = lo;
            float v2[8] = {rb2.x, rb2.y, rb2.z, rb2.w, rb3.x, rb3.y, rb3.z, rb3.w};
            conv8(v2, &hi, &lo);
            *(uint4*)(sBh + (rB + 16) * 256 + c1o) = hi;
            *(uint4*)(sBl + (rB + 16) * 256 + c1o) = lo;
        }
        __syncthreads();
        if (kc < 7) {
            const float* pa = Sb + (kc + 1) * 32;
            const float* pb = Qb + (size_t)(kc + 1) * 32 * DD;
            ra0 = *(const float4*)(pa);                   ra1 = *(const float4*)(pa + 4);
            ra2 = *(const float4*)(pa + (size_t)64 * JJ); ra3 = *(const float4*)(pa + (size_t)64 * JJ + 4);
            rb0 = *(const float4*)(pb);                   rb1 = *(const float4*)(pb + 4);
            rb2 = *(const float4*)(pb + (size_t)16 * DD); rb3 = *(const float4*)(pb + (size_t)16 * DD + 4);
        }
#pragma unroll
        for (int ks = 0; ks < 2; ks++) {
            uint32_t Ah[4][4], Al[4][4], Bf[2][4];
            const int ca = ks * 2 + ack;
            const int krow = ks * 16 + bkrow;
#pragma unroll
            for (int mi = 0; mi < 4; mi++)
                ldmx4(Ah[mi], sAb + (arow + mi * 16) * 128 + ((ca ^ lsw) << 4));
#pragma unroll
            for (int mi = 0; mi < 4; mi++)
                ldmx4(Al[mi], sAb + (arow + mi * 16) * 128 + (((ca + 4) ^ lsw) << 4));
#pragma unroll
            for (int n2 = 0; n2 < 2; n2++) {
                const int cn = bcn + n2 * 2;
                const int co = (((cn ^ lsw) & 7) | (cn & 8)) << 4;
                ldmx4t(Bf[n2], sBhb + krow * 256 + co);
            }
#pragma unroll
            for (int mi = 0; mi < 4; mi++)
#pragma unroll
                for (int ni = 0; ni < 4; ni++) {
                    const uint32_t* bp = &Bf[ni >> 1][(ni & 1) * 2];
                    mma_bf16(acc[mi][ni], Ah[mi], bp[0], bp[1]);
                }
#pragma unroll
            for (int mi = 0; mi < 4; mi++)
#pragma unroll
                for (int ni = 0; ni < 4; ni++) {
                    const uint32_t* bp = &Bf[ni >> 1][(ni & 1) * 2];
                    mma_bf16(acc[mi][ni], Al[mi], bp[0], bp[1]);
                }
#pragma unroll
            for (int n2 = 0; n2 < 2; n2++) {
                const int cn = bcn + n2 * 2;
                const int co = (((cn ^ lsw) & 7) | (cn & 8)) << 4;
                ldmx4t(Bf[n2], sBlb + krow * 256 + co);
            }
#pragma unroll
            for (int mi = 0; mi < 4; mi++)
#pragma unroll
                for (int ni = 0; ni < 4; ni++) {
                    const uint32_t* bp = &Bf[ni >> 1][(ni & 1) * 2];
                    mma_bf16(acc[mi][ni], Ah[mi], bp[0], bp[1]);
                }
        }
    }

    // stage U into smem, then coalesced G epilogue
    __syncthreads();
    float* st = (float*)us;
    const int g = lane >> 2, tc = (lane & 3) * 2;
#pragma unroll
    for (int mi = 0; mi < 4; mi++) {
        const int r0 = wm * 64 + mi * 16 + g;
#pragma unroll
        for (int ni = 0; ni < 4; ni++) {
            const int cl = wn * 32 + ni * 8 + tc;
            st[r0 * 128 + cl] = acc[mi][ni][0];
            st[r0 * 128 + cl + 1] = acc[mi][ni][1];
            st[(r0 + 8) * 128 + cl] = acc[mi][ni][2];
            st[(r0 + 8) * 128 + cl + 1] = acc[mi][ni][3];
        }
    }
    __syncthreads();
#pragma unroll
    for (int it = 0; it < 16; it++) {
        const int idx = it * 256 + tid;
        const int r = idx >> 5, c4 = (idx & 31) * 4;
        float4 u4 = *(float4*)&st[r * 128 + c4];
        float4 cv = *(const float4*)(C + ((size_t)(b * TT + t0 + r)) * DD + d0 + c4);
        float4 h4 = *(const float4*)&hs[c4];
        float* grow = G + ((size_t)(b * TT + t0 + r)) * (4 * DD);
        *(float4*)(grow + d0 + c4) = cv;
        *(float4*)(grow + DD + d0 + c4) = u4;
        *(float4*)(grow + 2 * DD + d0 + c4) =
            make_float4(cv.x * u4.x, cv.y * u4.y, cv.z * u4.z, cv.w * u4.w);
        *(float4*)(grow + 3 * DD + d0 + c4) =
            make_float4(cv.x * h4.x, cv.y * h4.y, cv.z * h4.z, cv.w * h4.w);
    }
}

// ---------------- launch ----------------------------------------------------
extern "C" void kernel_launch(void* const* d_in, const int* in_sizes, int n_in,
                              void* d_out, int out_size) {
    const float* C  = (const float*)d_in[0];
    const float* Q  = (const float*)d_in[1];
    const float* wa = (const float*)d_in[2];
    float* G = (float*)d_out;

    cudaFuncSetAttribute(k_u_mma, cudaFuncAttributeMaxDynamicSharedMemorySize, U_DSMEM);

    float* d_c1; cudaGetSymbolAddress((void**)&d_c1, g_c1);
    float* d_q2; cudaGetSymbolAddress((void**)&d_q2, g_q2);

    k_rowdot<<<(BB * TT) / 8, 256>>>(C, wa, d_c1, BB * TT);
    k_rowdot<<<(BB * JJ) / 8, 256>>>(Q, wa + DD, d_q2, BB * JJ);

    dim3 gs(JJ / 128, TT / 128, BB);
    k_s_mma<<<gs, 256>>>(C, Q, wa + 2 * DD);

    k_rowmax<<<(BB * TT) / 8, 256>>>();
    dim3 g2(NCHUNK, BB);
    k_colstats<<<g2, 256>>>();
    k_colcombine<<<BB, 256>>>();
    k_bt<<<BB, 256>>>();
    k_hpart<<<g2, 256>>>(C);
    k_hcombine<<<BB, 512>>>();

    dim3 gu(DD / 128, TT / 128, BB);
    k_u_mma<<<gu, 256, U_DSMEM>>>(C, Q, G);
}